// round 5
// baseline (speedup 1.0000x reference)
#include <cuda_runtime.h>
#include <cuda_fp16.h>
#include <stdint.h>

#define USER_NUM 100000
#define ITEM_NUM 200000
#define NNODES   (USER_NUM + ITEM_NUM)   // 300000
#define EMB      64
#define TOT      (NNODES * EMB)
#define ELLW     32                      // max degree slot count (Poisson mean 4.17)

// ---- static scratch (no cudaMalloc allowed) ----
__device__ int   g_deg[NNODES];            // fill cursor, then degree
__device__ int2  g_ell[(size_t)NNODES * ELLW];   // packed (col, val-as-bits), row stride 256B
__device__ uint4 g_bufA[TOT / 8];          // fp16 e2  (row = 8 uint4 = 64 halfs)
__device__ uint4 g_bufB[TOT / 8];          // fp16 e1

// ---------------------------------------------------------------------------
__global__ void zero_deg_kernel(int* __restrict__ deg) {
    int i = blockIdx.x * blockDim.x + threadIdx.x;
    if (i < NNODES) deg[i] = 0;
}

__global__ void fill_ell_kernel(const int* __restrict__ rows, const int* __restrict__ cols,
                                const float* __restrict__ vals,
                                int* __restrict__ deg, int2* __restrict__ ell, int n) {
    int e = blockIdx.x * blockDim.x + threadIdx.x;
    if (e >= n) return;
    int r = rows[e];
    int pos = atomicAdd(&deg[r], 1);
    if (pos < ELLW)
        ell[(size_t)r * ELLW + pos] = make_int2(cols[e], __float_as_int(vals[e]));
}

// ---------------------------------------------------------------------------
// helpers: fp16x8 <-> fp32x8
__device__ __forceinline__ void unpack8(uint4 raw, float f[8]) {
    __half2 h0 = *reinterpret_cast<__half2*>(&raw.x);
    __half2 h1 = *reinterpret_cast<__half2*>(&raw.y);
    __half2 h2 = *reinterpret_cast<__half2*>(&raw.z);
    __half2 h3 = *reinterpret_cast<__half2*>(&raw.w);
    float2 f0 = __half22float2(h0), f1 = __half22float2(h1);
    float2 f2 = __half22float2(h2), f3 = __half22float2(h3);
    f[0]=f0.x; f[1]=f0.y; f[2]=f1.x; f[3]=f1.y;
    f[4]=f2.x; f[5]=f2.y; f[6]=f3.x; f[7]=f3.y;
}
__device__ __forceinline__ uint4 pack8(const float f[8]) {
    __half2 h0 = __float22half2_rn(make_float2(f[0], f[1]));
    __half2 h1 = __float22half2_rn(make_float2(f[2], f[3]));
    __half2 h2 = __float22half2_rn(make_float2(f[4], f[5]));
    __half2 h3 = __float22half2_rn(make_float2(f[6], f[7]));
    uint4 o;
    o.x = *reinterpret_cast<unsigned*>(&h0);
    o.y = *reinterpret_cast<unsigned*>(&h1);
    o.z = *reinterpret_cast<unsigned*>(&h2);
    o.w = *reinterpret_cast<unsigned*>(&h3);
    return o;
}

// ---------------------------------------------------------------------------
// ELL SpMM: 8 lanes per row, 8 floats per lane.
//   MODE 0: gather fp32 ego (user||item)  -> write fp16 next
//   MODE 1: gather fp16 x                 -> write fp16 next
//   MODE 2: gather fp16 x ; epilogue out = (ego + B + A + s) * 0.25  (fp32)
// ---------------------------------------------------------------------------
template <int MODE>
__global__ __launch_bounds__(256) void spmm_ell_kernel(
        const int*  __restrict__ deg,
        const int2* __restrict__ ell,
        const uint4* __restrict__ xh,       // fp16 gather src (MODE 1/2)
        const float4* __restrict__ user,
        const float4* __restrict__ item,
        uint4* __restrict__ nexth,          // fp16 out (MODE 0/1)
        const uint4* __restrict__ bh,       // e1 (MODE 2)
        const uint4* __restrict__ ah,       // e2 (MODE 2)
        float4* __restrict__ out) {
    int t = blockIdx.x * blockDim.x + threadIdx.x;
    int r = t >> 3;
    int l = t & 7;
    if (r >= NNODES) return;

    int d = __ldg(deg + r);
    if (d > ELLW) d = ELLW;
    const int2* cv = ell + (size_t)r * ELLW;

    float a[8];
#pragma unroll
    for (int j = 0; j < 8; ++j) a[j] = 0.f;

    for (int i = 0; i < d; ++i) {
        int2 c = __ldg(cv + i);
        float v = __int_as_float(c.y);
        if (MODE == 0) {
            const float4* src = (c.x < USER_NUM)
                ? (user + (size_t)c.x * 16 + l * 2)
                : (item + (size_t)(c.x - USER_NUM) * 16 + l * 2);
            float4 x0 = __ldg(src);
            float4 x1 = __ldg(src + 1);
            a[0] += v * x0.x; a[1] += v * x0.y; a[2] += v * x0.z; a[3] += v * x0.w;
            a[4] += v * x1.x; a[5] += v * x1.y; a[6] += v * x1.z; a[7] += v * x1.w;
        } else {
            uint4 raw = __ldg(xh + (size_t)c.x * 8 + l);
            float xf[8];
            unpack8(raw, xf);
#pragma unroll
            for (int j = 0; j < 8; ++j) a[j] += v * xf[j];
        }
    }

    if (MODE == 2) {
        size_t fo = (size_t)r * 16 + l * 2;   // float4 index into [N,64]
        const float4* egop = (r < USER_NUM)
            ? (user + fo)
            : (item + (size_t)(r - USER_NUM) * 16 + l * 2);
        float4 e0 = __ldg(egop);
        float4 e1 = __ldg(egop + 1);
        float bf[8], af[8];
        unpack8(__ldg(bh + (size_t)r * 8 + l), bf);
        unpack8(__ldg(ah + (size_t)r * 8 + l), af);
        float4 o0, o1;
        o0.x = (e0.x + bf[0] + af[0] + a[0]) * 0.25f;
        o0.y = (e0.y + bf[1] + af[1] + a[1]) * 0.25f;
        o0.z = (e0.z + bf[2] + af[2] + a[2]) * 0.25f;
        o0.w = (e0.w + bf[3] + af[3] + a[3]) * 0.25f;
        o1.x = (e1.x + bf[4] + af[4] + a[4]) * 0.25f;
        o1.y = (e1.y + bf[5] + af[5] + a[5]) * 0.25f;
        o1.z = (e1.z + bf[6] + af[6] + a[6]) * 0.25f;
        o1.w = (e1.w + bf[7] + af[7] + a[7]) * 0.25f;
        out[fo]     = o0;
        out[fo + 1] = o1;
    } else {
        nexth[(size_t)r * 8 + l] = pack8(a);
    }
}

// ---------------------------------------------------------------------------
extern "C" void kernel_launch(void* const* d_in, const int* in_sizes, int n_in,
                              void* d_out, int out_size) {
    const float* user = (const float*)d_in[0];
    const float* item = (const float*)d_in[1];
    const float* vals = (const float*)d_in[2];
    const int*   rows = (const int*)  d_in[3];
    const int*   cols = (const int*)  d_in[4];
    const int n_edges = in_sizes[2];

    float4* out = (float4*)d_out;

    int  *deg;
    int2 *ell;
    uint4 *A, *B;
    cudaGetSymbolAddress((void**)&deg, g_deg);
    cudaGetSymbolAddress((void**)&ell, g_ell);
    cudaGetSymbolAddress((void**)&A,   g_bufA);
    cudaGetSymbolAddress((void**)&B,   g_bufB);

    const int TPB = 256;
    const int grid_nodes = (NNODES + TPB - 1) / TPB;
    const int grid_edges = (n_edges + TPB - 1) / TPB;
    const int grid_spmm  = (NNODES * 8 + TPB - 1) / TPB;

    // ---- ELL build (2 kernels) ----
    zero_deg_kernel<<<grid_nodes, TPB>>>(deg);
    fill_ell_kernel<<<grid_edges, TPB>>>(rows, cols, vals, deg, ell, n_edges);

    // ---- 3 propagation layers ----
    // layer 1: B = Adj*ego              (fp16 out, no acc traffic)
    spmm_ell_kernel<0><<<grid_spmm, TPB>>>(deg, ell, nullptr,
                                           (const float4*)user, (const float4*)item,
                                           B, nullptr, nullptr, nullptr);
    // layer 2: A = Adj*B                (fp16 in/out)
    spmm_ell_kernel<1><<<grid_spmm, TPB>>>(deg, ell, B,
                                           (const float4*)user, (const float4*)item,
                                           A, nullptr, nullptr, nullptr);
    // layer 3: out = (ego + B + A + Adj*A) * 0.25
    spmm_ell_kernel<2><<<grid_spmm, TPB>>>(deg, ell, A,
                                           (const float4*)user, (const float4*)item,
                                           nullptr, B, A, out);
}

// round 6
// speedup vs baseline: 1.1451x; 1.1451x over previous
#include <cuda_runtime.h>
#include <cuda_fp16.h>
#include <stdint.h>

#define USER_NUM 100000
#define ITEM_NUM 200000
#define NNODES   (USER_NUM + ITEM_NUM)   // 300000
#define EMB      64
#define TOT      (NNODES * EMB)
#define MAXE     2097152

#define SCAN_TPB 1024
#define NSCANBLK ((NNODES + SCAN_TPB - 1) / SCAN_TPB)   // 293

// ---- static scratch (no cudaMalloc allowed) ----
__device__ int   g_counts[NNODES];
__device__ int   g_offsets[NNODES + 1];
__device__ int   g_blocksums[512];
__device__ int2  g_csr_cv[MAXE];           // packed (col, val-as-bits)
__device__ uint4 g_bufA[TOT / 8];          // fp16 e2  (row = 8 uint4 = 64 halfs)
__device__ uint4 g_bufB[TOT / 8];          // fp16 e1

// ---------------------------------------------------------------------------
__global__ void zero_counts_kernel(int* __restrict__ counts) {
    int i = blockIdx.x * blockDim.x + threadIdx.x;
    if (i < NNODES) counts[i] = 0;
}

__global__ void hist_kernel(const int* __restrict__ rows, int* __restrict__ counts, int n) {
    int i = blockIdx.x * blockDim.x + threadIdx.x;
    if (i < n) atomicAdd(&counts[rows[i]], 1);
}

__global__ void scan1_kernel(int* __restrict__ counts, int* __restrict__ offsets,
                             int* __restrict__ blocksums) {
    __shared__ int sh[SCAN_TPB];
    int tid = threadIdx.x;
    int gid = blockIdx.x * SCAN_TPB + tid;
    int v = (gid < NNODES) ? counts[gid] : 0;
    sh[tid] = v;
    __syncthreads();
    for (int off = 1; off < SCAN_TPB; off <<= 1) {
        int t = (tid >= off) ? sh[tid - off] : 0;
        __syncthreads();
        sh[tid] += t;
        __syncthreads();
    }
    if (gid < NNODES) {
        offsets[gid] = sh[tid] - v;
        counts[gid]  = 0;             // becomes fill cursor
    }
    if (tid == SCAN_TPB - 1) blocksums[blockIdx.x] = sh[tid];
}

__global__ void scan2_kernel(int* __restrict__ blocksums, int nblk) {
    __shared__ int sh[512];
    int tid = threadIdx.x;
    int v = (tid < nblk) ? blocksums[tid] : 0;
    sh[tid] = v;
    __syncthreads();
    for (int off = 1; off < 512; off <<= 1) {
        int t = (tid >= off) ? sh[tid - off] : 0;
        __syncthreads();
        sh[tid] += t;
        __syncthreads();
    }
    if (tid < nblk) blocksums[tid] = sh[tid] - v;
}

__global__ void scan3_kernel(int* __restrict__ offsets, const int* __restrict__ blocksums,
                             int n_edges) {
    int gid = blockIdx.x * SCAN_TPB + threadIdx.x;
    if (gid < NNODES) offsets[gid] += blocksums[blockIdx.x];
    if (gid == 0) offsets[NNODES] = n_edges;
}

__global__ void fill_kernel(const int* __restrict__ rows, const int* __restrict__ cols,
                            const float* __restrict__ vals,
                            const int* __restrict__ offsets, int* __restrict__ cursor,
                            int2* __restrict__ csr_cv, int n) {
    int e = blockIdx.x * blockDim.x + threadIdx.x;
    if (e >= n) return;
    int r = rows[e];
    int pos = offsets[r] + atomicAdd(&cursor[r], 1);
    csr_cv[pos] = make_int2(cols[e], __float_as_int(vals[e]));
}

// ---------------------------------------------------------------------------
__device__ __forceinline__ uint4 pack8(const float f[8]) {
    __half2 h0 = __float22half2_rn(make_float2(f[0], f[1]));
    __half2 h1 = __float22half2_rn(make_float2(f[2], f[3]));
    __half2 h2 = __float22half2_rn(make_float2(f[4], f[5]));
    __half2 h3 = __float22half2_rn(make_float2(f[6], f[7]));
    uint4 o;
    o.x = *reinterpret_cast<unsigned*>(&h0);
    o.y = *reinterpret_cast<unsigned*>(&h1);
    o.z = *reinterpret_cast<unsigned*>(&h2);
    o.w = *reinterpret_cast<unsigned*>(&h3);
    return o;
}
__device__ __forceinline__ void hacc4(__half2 acc[4], uint4 raw, __half2 vh) {
    __half2* h = reinterpret_cast<__half2*>(&raw);
#pragma unroll
    for (int j = 0; j < 4; ++j) acc[j] = __hfma2(vh, h[j], acc[j]);
}

// ---------------------------------------------------------------------------
// CSR SpMM, 8 lanes/row.
//   MODE 0: fp32 ego gather, fp32 acc, x2 edge batch -> fp16 store
//   MODE 1: fp16 gather, HFMA2 acc, x4 edge batch    -> fp16 store (raw acc)
//   MODE 2: like 1, epilogue out = (ego + B + A + s) * 0.25 (fp32)
// ---------------------------------------------------------------------------
template <int MODE>
__global__ __launch_bounds__(256) void spmm_csr_kernel(
        const int*  __restrict__ offsets,
        const int2* __restrict__ cv,
        const uint4* __restrict__ xh,
        const float4* __restrict__ user,
        const float4* __restrict__ item,
        uint4* __restrict__ nexth,
        const uint4* __restrict__ bh,
        const uint4* __restrict__ ah,
        float4* __restrict__ out) {
    int t = blockIdx.x * blockDim.x + threadIdx.x;
    int r = t >> 3;
    int l = t & 7;
    if (r >= NNODES) return;

    int s = __ldg(offsets + r);
    int e = __ldg(offsets + r + 1);

    if (MODE == 0) {
        float a[8];
#pragma unroll
        for (int j = 0; j < 8; ++j) a[j] = 0.f;
        int i = s;
        for (; i + 2 <= e; i += 2) {
            int2 c0 = __ldg(cv + i);
            int2 c1 = __ldg(cv + i + 1);
            const float4* s0 = (c0.x < USER_NUM)
                ? (user + (size_t)c0.x * 16 + l * 2)
                : (item + (size_t)(c0.x - USER_NUM) * 16 + l * 2);
            const float4* s1 = (c1.x < USER_NUM)
                ? (user + (size_t)c1.x * 16 + l * 2)
                : (item + (size_t)(c1.x - USER_NUM) * 16 + l * 2);
            float4 x00 = __ldg(s0), x01 = __ldg(s0 + 1);
            float4 x10 = __ldg(s1), x11 = __ldg(s1 + 1);
            float v0 = __int_as_float(c0.y), v1 = __int_as_float(c1.y);
            a[0] += v0*x00.x + v1*x10.x;  a[1] += v0*x00.y + v1*x10.y;
            a[2] += v0*x00.z + v1*x10.z;  a[3] += v0*x00.w + v1*x10.w;
            a[4] += v0*x01.x + v1*x11.x;  a[5] += v0*x01.y + v1*x11.y;
            a[6] += v0*x01.z + v1*x11.z;  a[7] += v0*x01.w + v1*x11.w;
        }
        if (i < e) {
            int2 c0 = __ldg(cv + i);
            const float4* s0 = (c0.x < USER_NUM)
                ? (user + (size_t)c0.x * 16 + l * 2)
                : (item + (size_t)(c0.x - USER_NUM) * 16 + l * 2);
            float4 x0 = __ldg(s0), x1 = __ldg(s0 + 1);
            float v0 = __int_as_float(c0.y);
            a[0] += v0*x0.x; a[1] += v0*x0.y; a[2] += v0*x0.z; a[3] += v0*x0.w;
            a[4] += v0*x1.x; a[5] += v0*x1.y; a[6] += v0*x1.z; a[7] += v0*x1.w;
        }
        nexth[(size_t)r * 8 + l] = pack8(a);
        return;
    }

    // MODE 1 / 2: half2 accumulation, x4 edge batch
    __half2 acc[4];
#pragma unroll
    for (int j = 0; j < 4; ++j) acc[j] = __half2half2(__float2half_rn(0.f));

    int i = s;
    for (; i + 4 <= e; i += 4) {
        int2 c0 = __ldg(cv + i);
        int2 c1 = __ldg(cv + i + 1);
        int2 c2 = __ldg(cv + i + 2);
        int2 c3 = __ldg(cv + i + 3);
        uint4 r0 = __ldg(xh + (size_t)c0.x * 8 + l);
        uint4 r1 = __ldg(xh + (size_t)c1.x * 8 + l);
        uint4 r2 = __ldg(xh + (size_t)c2.x * 8 + l);
        uint4 r3 = __ldg(xh + (size_t)c3.x * 8 + l);
        hacc4(acc, r0, __half2half2(__float2half_rn(__int_as_float(c0.y))));
        hacc4(acc, r1, __half2half2(__float2half_rn(__int_as_float(c1.y))));
        hacc4(acc, r2, __half2half2(__float2half_rn(__int_as_float(c2.y))));
        hacc4(acc, r3, __half2half2(__float2half_rn(__int_as_float(c3.y))));
    }
    for (; i < e; ++i) {
        int2 c0 = __ldg(cv + i);
        uint4 r0 = __ldg(xh + (size_t)c0.x * 8 + l);
        hacc4(acc, r0, __half2half2(__float2half_rn(__int_as_float(c0.y))));
    }

    if (MODE == 1) {
        uint4 o;
        o.x = *reinterpret_cast<unsigned*>(&acc[0]);
        o.y = *reinterpret_cast<unsigned*>(&acc[1]);
        o.z = *reinterpret_cast<unsigned*>(&acc[2]);
        o.w = *reinterpret_cast<unsigned*>(&acc[3]);
        nexth[(size_t)r * 8 + l] = o;
    } else {
        size_t fo = (size_t)r * 16 + l * 2;
        const float4* egop = (r < USER_NUM)
            ? (user + fo)
            : (item + (size_t)(r - USER_NUM) * 16 + l * 2);
        float4 e0 = __ldg(egop);
        float4 e1 = __ldg(egop + 1);
        uint4 braw = __ldg(bh + (size_t)r * 8 + l);
        uint4 araw = __ldg(ah + (size_t)r * 8 + l);
        __half2* bhh = reinterpret_cast<__half2*>(&braw);
        __half2* ahh = reinterpret_cast<__half2*>(&araw);
        float2 b0 = __half22float2(bhh[0]), b1 = __half22float2(bhh[1]);
        float2 b2 = __half22float2(bhh[2]), b3 = __half22float2(bhh[3]);
        float2 a0 = __half22float2(ahh[0]), a1 = __half22float2(ahh[1]);
        float2 a2 = __half22float2(ahh[2]), a3 = __half22float2(ahh[3]);
        float2 s0 = __half22float2(acc[0]), s1 = __half22float2(acc[1]);
        float2 s2 = __half22float2(acc[2]), s3 = __half22float2(acc[3]);
        float4 o0, o1;
        o0.x = (e0.x + b0.x + a0.x + s0.x) * 0.25f;
        o0.y = (e0.y + b0.y + a0.y + s0.y) * 0.25f;
        o0.z = (e0.z + b1.x + a1.x + s1.x) * 0.25f;
        o0.w = (e0.w + b1.y + a1.y + s1.y) * 0.25f;
        o1.x = (e1.x + b2.x + a2.x + s2.x) * 0.25f;
        o1.y = (e1.y + b2.y + a2.y + s2.y) * 0.25f;
        o1.z = (e1.z + b3.x + a3.x + s3.x) * 0.25f;
        o1.w = (e1.w + b3.y + a3.y + s3.y) * 0.25f;
        out[fo]     = o0;
        out[fo + 1] = o1;
    }
}

// ---------------------------------------------------------------------------
extern "C" void kernel_launch(void* const* d_in, const int* in_sizes, int n_in,
                              void* d_out, int out_size) {
    const float* user = (const float*)d_in[0];
    const float* item = (const float*)d_in[1];
    const float* vals = (const float*)d_in[2];
    const int*   rows = (const int*)  d_in[3];
    const int*   cols = (const int*)  d_in[4];
    const int n_edges = in_sizes[2];

    float4* out = (float4*)d_out;

    int *counts, *offsets, *blocksums;
    int2 *csr_cv;
    uint4 *A, *B;
    cudaGetSymbolAddress((void**)&counts,    g_counts);
    cudaGetSymbolAddress((void**)&offsets,   g_offsets);
    cudaGetSymbolAddress((void**)&blocksums, g_blocksums);
    cudaGetSymbolAddress((void**)&csr_cv,    g_csr_cv);
    cudaGetSymbolAddress((void**)&A,         g_bufA);
    cudaGetSymbolAddress((void**)&B,         g_bufB);

    const int TPB = 256;
    const int grid_nodes = (NNODES + TPB - 1) / TPB;
    const int grid_edges = (n_edges + TPB - 1) / TPB;
    const int grid_spmm  = (NNODES * 8 + TPB - 1) / TPB;

    // ---- CSR build ----
    zero_counts_kernel<<<grid_nodes, TPB>>>(counts);
    hist_kernel<<<grid_edges, TPB>>>(rows, counts, n_edges);
    scan1_kernel<<<NSCANBLK, SCAN_TPB>>>(counts, offsets, blocksums);
    scan2_kernel<<<1, 512>>>(blocksums, NSCANBLK);
    scan3_kernel<<<NSCANBLK, SCAN_TPB>>>(offsets, blocksums, n_edges);
    fill_kernel<<<grid_edges, TPB>>>(rows, cols, vals, offsets, counts,
                                     csr_cv, n_edges);

    // ---- 3 propagation layers ----
    spmm_csr_kernel<0><<<grid_spmm, TPB>>>(offsets, csr_cv, nullptr,
                                           (const float4*)user, (const float4*)item,
                                           B, nullptr, nullptr, nullptr);
    spmm_csr_kernel<1><<<grid_spmm, TPB>>>(offsets, csr_cv, B,
                                           (const float4*)user, (const float4*)item,
                                           A, nullptr, nullptr, nullptr);
    spmm_csr_kernel<2><<<grid_spmm, TPB>>>(offsets, csr_cv, A,
                                           (const float4*)user, (const float4*)item,
                                           nullptr, B, A, out);
}